// round 2
// baseline (speedup 1.0000x reference)
#include <cuda_runtime.h>

#define N_NODES 50000
#define N_EDGES 600000
#define F_IN 64
#define N_GRAPHS 2000
#define BN_EPS 1e-5f

// ---------------- scratch (device globals; referenced by symbol, no alloc) --
__device__ float g_h[(size_t)N_NODES * 128];   // GEMM1 out / post-BN activ
__device__ float g_h2[(size_t)N_NODES * 64];   // GEMM2 out
__device__ float g_z[(size_t)N_NODES * 128];   // pre-BN accumulation buffer
__device__ float g_cnt[N_NODES];               // in-degree (edge dst counts)
__device__ float g_inv[N_NODES];               // 1/(deg+1)
__device__ float g_dinv[N_NODES];              // rsqrt(deg+1)
__device__ float g_gcnt[N_GRAPHS];             // nodes per graph
__device__ float g_pool[N_GRAPHS * 128];       // concat pooled features
__device__ float g_cs[128];                    // BN column sums
__device__ float g_css[128];                   // BN column sums of squares
__device__ float g_mlp[N_GRAPHS * 64];
__device__ float g_ms[64];
__device__ float g_mss[64];

// ---------------- zero / count kernels -------------------------------------

__global__ void zero_pool_kernel() {
    int i = blockIdx.x * blockDim.x + threadIdx.x;
    if (i < N_GRAPHS * 128) g_pool[i] = 0.0f;
    if (i < N_GRAPHS) g_gcnt[i] = 0.0f;
}

__global__ void zero_cnt_kernel() {
    int i = blockIdx.x * blockDim.x + threadIdx.x;
    if (i < N_NODES) g_cnt[i] = 0.0f;
}

// which==0 -> g_cnt (edge dst), which==1 -> g_gcnt (batch)
__global__ void count_kernel(const int* __restrict__ idx, int n, int which) {
    int i = blockIdx.x * blockDim.x + threadIdx.x;
    if (i < n) {
        if (which) atomicAdd(&g_gcnt[idx[i]], 1.0f);
        else       atomicAdd(&g_cnt[idx[i]], 1.0f);
    }
}

// ---------------- GEMM + self-loop/bias init of z ---------------------------
// LAYER==1: reads X (arg), writes g_h and g_z; also computes deg transforms.
// LAYER==2: reads g_h,   writes g_h2 and g_z.
// Both: block 0 zeroes the BN stat accumulators (consumed by later kernels).
template <int K, int NOUT, int LAYER>
__global__ void gemm_kernel(const float* __restrict__ X, const float* __restrict__ W,
                            const float* __restrict__ bias) {
    __shared__ float Ws[K * NOUT];   // 32 KB for both instantiations
    int tid = threadIdx.x;
    for (int i = tid; i < K * NOUT; i += 128) Ws[i] = W[i];
    if (blockIdx.x == 0) { g_cs[tid] = 0.0f; g_css[tid] = 0.0f; }
    __syncthreads();

    int r = blockIdx.x * 128 + tid;
    if (r >= N_NODES) return;

    float inv;
    if (LAYER == 1) {
        float d = g_cnt[r] + 1.0f;
        inv = 1.0f / d;
        g_inv[r] = inv;
        g_dinv[r] = rsqrtf(d);
    } else {
        inv = g_inv[r];
    }

    const float* xr = (LAYER == 1) ? (X + (size_t)r * K) : (g_h + (size_t)r * K);
    float* hout = (LAYER == 1) ? (g_h + (size_t)r * NOUT) : (g_h2 + (size_t)r * NOUT);
    float* zout = g_z + (size_t)r * NOUT;

    for (int j0 = 0; j0 < NOUT; j0 += 32) {
        float acc[32];
#pragma unroll
        for (int jj = 0; jj < 32; jj++) acc[jj] = 0.0f;
#pragma unroll 4
        for (int k = 0; k < K; k++) {
            float xk = xr[k];
#pragma unroll
            for (int jj = 0; jj < 32; jj += 4) {
                float4 w4 = *reinterpret_cast<const float4*>(&Ws[k * NOUT + j0 + jj]);
                acc[jj + 0] += xk * w4.x;
                acc[jj + 1] += xk * w4.y;
                acc[jj + 2] += xk * w4.z;
                acc[jj + 3] += xk * w4.w;
            }
        }
#pragma unroll
        for (int jj = 0; jj < 32; jj += 4) {
            float4 h4 = make_float4(acc[jj], acc[jj + 1], acc[jj + 2], acc[jj + 3]);
            *reinterpret_cast<float4*>(&hout[j0 + jj]) = h4;
            float4 b4 = *reinterpret_cast<const float4*>(&bias[j0 + jj]);
            float4 z4 = make_float4(fmaf(h4.x, inv, b4.x), fmaf(h4.y, inv, b4.y),
                                    fmaf(h4.z, inv, b4.z), fmaf(h4.w, inv, b4.w));
            *reinterpret_cast<float4*>(&zout[j0 + jj]) = z4;
        }
    }
}

// ---------------- edge aggregation (vector RED atomics) ---------------------
// g_z[dst] += H[src] * dinv[src]*dinv[dst];  NF/4 lanes per edge, float4 REDs.
template <int NF>
__global__ void edge_agg_kernel(const int* __restrict__ src, const int* __restrict__ dst) {
    const int TPE = NF / 4;
    const float* H = (NF == 128) ? g_h : g_h2;
    int gtid = blockIdx.x * blockDim.x + threadIdx.x;
    int lane = gtid & (TPE - 1);
    int e = gtid / TPE;
    int estride = (gridDim.x * blockDim.x) / TPE;
    for (; e < N_EDGES; e += estride) {
        int s = __ldg(&src[e]);
        int d = __ldg(&dst[e]);
        float norm = g_dinv[s] * g_dinv[d];
        float4 h4 = *reinterpret_cast<const float4*>(&H[(size_t)s * NF + lane * 4]);
        float* ap = &g_z[(size_t)d * NF + lane * 4];
        asm volatile("red.global.add.v4.f32 [%0], {%1, %2, %3, %4};"
                     :: "l"(ap), "f"(h4.x * norm), "f"(h4.y * norm),
                        "f"(h4.z * norm), "f"(h4.w * norm)
                     : "memory");
    }
}

// ---------------- BN column stats -------------------------------------------
template <int NF>
__global__ void stats_kernel() {
    int c = threadIdx.x;   // blockDim == NF
    float s = 0.0f, s2 = 0.0f;
    for (int r = blockIdx.x; r < N_NODES; r += gridDim.x) {
        float z = g_z[(size_t)r * NF + c];
        s += z; s2 += z * z;
    }
    atomicAdd(&g_cs[c], s);
    atomicAdd(&g_css[c], s2);
}

// ---------------- BN + ReLU (layer 1, 128 feats) -> g_h ---------------------
__global__ void bn_relu128_kernel(const float* __restrict__ gamma,
                                  const float* __restrict__ beta) {
    const float invN = 1.0f / (float)N_NODES;
    int total = N_NODES * 128;
    for (int i = blockIdx.x * blockDim.x + threadIdx.x; i < total;
         i += gridDim.x * blockDim.x) {
        int c = i & 127;
        float m = g_cs[c] * invN;
        float v = g_css[c] * invN - m * m;
        float y = (g_z[i] - m) * rsqrtf(v + BN_EPS) * gamma[c] + beta[c];
        g_h[i] = fmaxf(y, 0.0f);
    }
}

// ---------------- BN + ReLU + mean-pool (layer 2, 64 feats) -----------------
__global__ void bn_pool_kernel(const float* __restrict__ gamma,
                               const float* __restrict__ beta,
                               const int* __restrict__ batch, int off) {
    int c = threadIdx.x;   // blockDim == 64
    const float invN = 1.0f / (float)N_NODES;
    float m = g_cs[c] * invN;
    float rstd = rsqrtf(g_css[c] * invN - m * m + BN_EPS);
    float ga = gamma[c], be = beta[c];
    for (int r = blockIdx.x; r < N_NODES; r += gridDim.x) {
        float y = (g_z[(size_t)r * 64 + c] - m) * rstd * ga + be;
        y = fmaxf(y, 0.0f);
        atomicAdd(&g_pool[(size_t)batch[r] * 128 + off + c], y);
    }
}

// ---------------- MLP head ---------------------------------------------------
__global__ void mlp1_kernel(const float* __restrict__ Wf1, const float* __restrict__ bf1) {
    __shared__ float p[128];
    int g = blockIdx.x;
    int j = threadIdx.x;   // 64
    if (g == 0) { g_ms[j] = 0.0f; g_mss[j] = 0.0f; }
    float cv = g_gcnt[g]; if (cv < 1.0f) cv = 1.0f;
    float inv = 1.0f / cv;
    p[j]      = g_pool[(size_t)g * 128 + j] * inv;
    p[j + 64] = g_pool[(size_t)g * 128 + 64 + j] * inv;
    __syncthreads();
    float acc = bf1[j];
    for (int k = 0; k < 128; k++) acc += p[k] * Wf1[k * 64 + j];
    g_mlp[(size_t)g * 64 + j] = acc;
}

__global__ void mlp_stats_kernel() {
    int j = threadIdx.x;   // 64
    float s = 0.0f, s2 = 0.0f;
    for (int g = blockIdx.x; g < N_GRAPHS; g += gridDim.x) {
        float v = g_mlp[(size_t)g * 64 + j];
        s += v; s2 += v * v;
    }
    atomicAdd(&g_ms[j], s);
    atomicAdd(&g_mss[j], s2);
}

__global__ void mlp2_kernel(const float* __restrict__ gf1, const float* __restrict__ bef1,
                            const float* __restrict__ Wf2, const float* __restrict__ bf2,
                            float* __restrict__ out) {
    int g = blockIdx.x * blockDim.x + threadIdx.x;
    if (g >= N_GRAPHS) return;
    const float invG = 1.0f / (float)N_GRAPHS;
    float acc = 0.0f;
#pragma unroll 8
    for (int j = 0; j < 64; j++) {
        float m = g_ms[j] * invG;
        float v = g_mss[j] * invG - m * m;
        float y = (g_mlp[(size_t)g * 64 + j] - m) * rsqrtf(v + BN_EPS) * gf1[j] + bef1[j];
        y = fmaxf(y, 0.0f);
        acc += y * Wf2[j];
    }
    out[g] = acc + bf2[0];
}

// ---------------- launch (pure kernel launches, nothing else) ---------------

extern "C" void kernel_launch(void* const* d_in, const int* in_sizes, int n_in,
                              void* d_out, int out_size) {
    const float* xc    = (const float*)d_in[0];
    const float* xs    = (const float*)d_in[1];
    const int*   eic   = (const int*)d_in[2];
    const int*   eis   = (const int*)d_in[3];
    const int*   batch = (const int*)d_in[4];

    const float* Wb[2][2]  = {{(const float*)d_in[5],  (const float*)d_in[9]},
                              {(const float*)d_in[13], (const float*)d_in[17]}};
    const float* bb[2][2]  = {{(const float*)d_in[6],  (const float*)d_in[10]},
                              {(const float*)d_in[14], (const float*)d_in[18]}};
    const float* gb[2][2]  = {{(const float*)d_in[7],  (const float*)d_in[11]},
                              {(const float*)d_in[15], (const float*)d_in[19]}};
    const float* beb[2][2] = {{(const float*)d_in[8],  (const float*)d_in[12]},
                              {(const float*)d_in[16], (const float*)d_in[20]}};
    const float* Wf1  = (const float*)d_in[21];
    const float* bf1  = (const float*)d_in[22];
    const float* gf1  = (const float*)d_in[23];
    const float* bef1 = (const float*)d_in[24];
    const float* Wf2  = (const float*)d_in[25];
    const float* bf2  = (const float*)d_in[26];
    float* out = (float*)d_out;

    const int GEMM_BLOCKS = (N_NODES + 127) / 128;

    zero_pool_kernel<<<(N_GRAPHS * 128 + 255) / 256, 256>>>();
    count_kernel<<<(N_NODES + 255) / 256, 256>>>(batch, N_NODES, 1);

    for (int b = 0; b < 2; b++) {
        const float* X   = b ? xs : xc;
        const int*   src = b ? eis : eic;
        const int*   dst = src + N_EDGES;

        zero_cnt_kernel<<<(N_NODES + 255) / 256, 256>>>();
        count_kernel<<<(N_EDGES + 255) / 256, 256>>>(dst, N_EDGES, 0);

        // layer 1: 64 -> 128
        gemm_kernel<64, 128, 1><<<GEMM_BLOCKS, 128>>>(X, Wb[b][0], bb[b][0]);
        edge_agg_kernel<128><<<4096, 256>>>(src, dst);
        stats_kernel<128><<<512, 128>>>();
        bn_relu128_kernel<<<2048, 256>>>(gb[b][0], beb[b][0]);

        // layer 2: 128 -> 64
        gemm_kernel<128, 64, 2><<<GEMM_BLOCKS, 128>>>(nullptr, Wb[b][1], bb[b][1]);
        edge_agg_kernel<64><<<4096, 256>>>(src, dst);
        stats_kernel<64><<<512, 64>>>();
        bn_pool_kernel<<<1024, 64>>>(gb[b][1], beb[b][1], batch, b * 64);
    }

    mlp1_kernel<<<N_GRAPHS, 64>>>(Wf1, bf1);
    mlp_stats_kernel<<<32, 64>>>();
    mlp2_kernel<<<(N_GRAPHS + 63) / 64, 64>>>(gf1, bef1, Wf2, bf2, out);
}

// round 4
// speedup vs baseline: 1.2168x; 1.2168x over previous
#include <cuda_runtime.h>

#define N_NODES 50000
#define N_EDGES 600000
#define F_IN 64
#define N_GRAPHS 2000
#define BN_EPS 1e-5f

// ---------------- scratch (device globals) ----------------------------------
__device__ float g_h[(size_t)N_NODES * 128];   // hs = h * dinv (layer1, 128)
__device__ float g_h2[(size_t)N_NODES * 64];   // hs2 = h2 * dinv (layer2, 64)
__device__ float g_z[(size_t)N_NODES * 128];   // pre-BN buffer (layer1 then layer2)
__device__ int   g_cnti[N_NODES];              // in-degree counts
__device__ float g_dinv[N_NODES];              // rsqrt(deg+1)
__device__ int   g_off[N_NODES + 1];           // CSR offsets
__device__ int   g_head[N_NODES];              // scatter heads
__device__ int   g_csrc[N_EDGES];              // CSR src indices (sorted by dst)
__device__ float g_gcnt[N_GRAPHS];
__device__ float g_pool[N_GRAPHS * 128];
__device__ float g_cs[128],  g_css[128];       // layer1 BN stats
__device__ float g_cs2[64],  g_css2[64];       // layer2 BN stats
__device__ float g_mlp[N_GRAPHS * 64];
__device__ float g_ms[64], g_mss[64];

// ---------------- small setup kernels ---------------------------------------

__global__ void zero_pool_kernel() {
    int i = blockIdx.x * blockDim.x + threadIdx.x;
    if (i < N_GRAPHS * 128) g_pool[i] = 0.0f;
    if (i < N_GRAPHS) g_gcnt[i] = 0.0f;
}

__global__ void count_batch_kernel(const int* __restrict__ batch) {
    int i = blockIdx.x * blockDim.x + threadIdx.x;
    if (i < N_NODES) atomicAdd(&g_gcnt[batch[i]], 1.0f);
}

__global__ void zero_cnt_kernel() {
    int i = blockIdx.x * blockDim.x + threadIdx.x;
    if (i < N_NODES) g_cnti[i] = 0;
}

__global__ void count_dst_kernel(const int* __restrict__ dst) {
    int i = blockIdx.x * blockDim.x + threadIdx.x;
    if (i < N_EDGES) atomicAdd(&g_cnti[dst[i]], 1);
}

// single-block scan: g_cnti -> g_off/g_head (exclusive), plus dinv
__global__ void scan_kernel() {
    __shared__ int wsum[32];
    __shared__ int carry_s;
    int tid = threadIdx.x, lane = tid & 31, w = tid >> 5;
    if (tid == 0) carry_s = 0;
    __syncthreads();
    for (int base = 0; base < N_NODES; base += 1024) {
        int i = base + tid;
        int c = (i < N_NODES) ? g_cnti[i] : 0;
        if (i < N_NODES) g_dinv[i] = rsqrtf((float)c + 1.0f);
        int v = c;
#pragma unroll
        for (int o = 1; o < 32; o <<= 1) {
            int t = __shfl_up_sync(~0u, v, o);
            if (lane >= o) v += t;
        }
        if (lane == 31) wsum[w] = v;
        __syncthreads();
        if (w == 0) {
            int s = wsum[lane];
#pragma unroll
            for (int o = 1; o < 32; o <<= 1) {
                int t = __shfl_up_sync(~0u, s, o);
                if (lane >= o) s += t;
            }
            wsum[lane] = s;
        }
        __syncthreads();
        int incl = carry_s + ((w > 0) ? wsum[w - 1] : 0) + v;
        if (i < N_NODES) { g_off[i] = incl - c; g_head[i] = incl - c; }
        __syncthreads();
        if (tid == 1023) carry_s = incl;
        __syncthreads();
    }
    if (threadIdx.x == 0) g_off[N_NODES] = carry_s;
}

__global__ void scatter_kernel(const int* __restrict__ src, const int* __restrict__ dst) {
    int e = blockIdx.x * blockDim.x + threadIdx.x;
    if (e < N_EDGES) {
        int slot = atomicAdd(&g_head[dst[e]], 1);
        g_csrc[slot] = src[e];
    }
}

// ---------------- GEMM1: hs = (X @ W1) * dinv;  also zeroes layer1 stats ----
__global__ void gemm1_kernel(const float* __restrict__ X, const float* __restrict__ W) {
    __shared__ float Ws[64 * 128];
    int tid = threadIdx.x;
    for (int i = tid; i < 64 * 128; i += 128) Ws[i] = W[i];
    if (blockIdx.x == 0) { g_cs[tid] = 0.0f; g_css[tid] = 0.0f; }
    __syncthreads();
    int r = blockIdx.x * 128 + tid;
    if (r >= N_NODES) return;
    float dv = g_dinv[r];
    const float* xr = X + (size_t)r * 64;
    float* yr = g_h + (size_t)r * 128;
    for (int j0 = 0; j0 < 128; j0 += 32) {
        float acc[32];
#pragma unroll
        for (int jj = 0; jj < 32; jj++) acc[jj] = 0.0f;
#pragma unroll 4
        for (int k = 0; k < 64; k++) {
            float xk = xr[k];
#pragma unroll
            for (int jj = 0; jj < 32; jj += 4) {
                float4 w4 = *reinterpret_cast<const float4*>(&Ws[k * 128 + j0 + jj]);
                acc[jj + 0] += xk * w4.x; acc[jj + 1] += xk * w4.y;
                acc[jj + 2] += xk * w4.z; acc[jj + 3] += xk * w4.w;
            }
        }
#pragma unroll
        for (int jj = 0; jj < 32; jj += 4) {
            float4 v = make_float4(acc[jj] * dv, acc[jj + 1] * dv,
                                   acc[jj + 2] * dv, acc[jj + 3] * dv);
            *reinterpret_cast<float4*>(&yr[j0 + jj]) = v;
        }
    }
}

// ---------------- GEMM2: hs2 = (relu(BN(z)) @ W2) * dinv; zeroes L2 stats ---
__global__ void gemm2_kernel(const float* __restrict__ W,
                             const float* __restrict__ gamma,
                             const float* __restrict__ beta) {
    __shared__ float Ws[128 * 64];
    __shared__ float a_s[128], b_s[128];
    int tid = threadIdx.x;
    for (int i = tid; i < 128 * 64; i += 128) Ws[i] = W[i];
    {
        const float invN = 1.0f / (float)N_NODES;
        float m = g_cs[tid] * invN;
        float v = g_css[tid] * invN - m * m;
        float a = rsqrtf(v + BN_EPS) * gamma[tid];
        a_s[tid] = a;
        b_s[tid] = beta[tid] - m * a;
    }
    if (blockIdx.x == 0 && tid < 64) { g_cs2[tid] = 0.0f; g_css2[tid] = 0.0f; }
    __syncthreads();
    int r = blockIdx.x * 128 + tid;
    if (r >= N_NODES) return;
    float dv = g_dinv[r];
    const float* zr = g_z + (size_t)r * 128;
    float* yr = g_h2 + (size_t)r * 64;
    for (int j0 = 0; j0 < 64; j0 += 32) {
        float acc[32];
#pragma unroll
        for (int jj = 0; jj < 32; jj++) acc[jj] = 0.0f;
#pragma unroll 4
        for (int k = 0; k < 128; k++) {
            float xk = fmaxf(fmaf(zr[k], a_s[k], b_s[k]), 0.0f);
#pragma unroll
            for (int jj = 0; jj < 32; jj += 4) {
                float4 w4 = *reinterpret_cast<const float4*>(&Ws[k * 64 + j0 + jj]);
                acc[jj + 0] += xk * w4.x; acc[jj + 1] += xk * w4.y;
                acc[jj + 2] += xk * w4.z; acc[jj + 3] += xk * w4.w;
            }
        }
#pragma unroll
        for (int jj = 0; jj < 32; jj += 4) {
            float4 v = make_float4(acc[jj] * dv, acc[jj + 1] * dv,
                                   acc[jj + 2] * dv, acc[jj + 3] * dv);
            *reinterpret_cast<float4*>(&yr[j0 + jj]) = v;
        }
    }
}

// ---------------- gather aggregation + BN stats ------------------------------
// z[r] = (Sum_{in-edges} hs[src] + hs[r]) * dinv[r] + bias; warp per node.
// NF=128: float4/lane; NF=64: float2/lane.  256 threads = 8 warps per block.
template <int NF>
__global__ void agg_kernel(const float* __restrict__ bias) {
    const int VEC = NF / 32;
    const float* Hs = (NF == 128) ? g_h : g_h2;
    float* CS  = (NF == 128) ? g_cs  : g_cs2;
    float* CSS = (NF == 128) ? g_css : g_css2;
    __shared__ float scs[8][NF];
    __shared__ float scss[8][NF];
    int tid = threadIdx.x, lane = tid & 31, w = tid >> 5;
    float b[VEC], s[VEC], s2[VEC];
#pragma unroll
    for (int v = 0; v < VEC; v++) {
        b[v] = bias[lane * VEC + v];
        s[v] = 0.0f; s2[v] = 0.0f;
    }
    for (int r = blockIdx.x * 8 + w; r < N_NODES; r += gridDim.x * 8) {
        int beg = g_off[r], end = g_off[r + 1];
        float acc[VEC], acc2[VEC];
        // self term
        if (VEC == 4) {
            float4 h4 = *reinterpret_cast<const float4*>(&Hs[(size_t)r * NF + lane * 4]);
            acc[0] = h4.x; acc[1] = h4.y; acc[2] = h4.z; acc[3] = h4.w;
        } else {
            float2 h2 = *reinterpret_cast<const float2*>(&Hs[(size_t)r * NF + lane * 2]);
            acc[0] = h2.x; acc[1] = h2.y;
        }
#pragma unroll
        for (int v = 0; v < VEC; v++) acc2[v] = 0.0f;
        int i = beg;
        for (; i + 1 < end; i += 2) {
            int s0 = g_csrc[i], s1 = g_csrc[i + 1];
            if (VEC == 4) {
                float4 a4 = *reinterpret_cast<const float4*>(&Hs[(size_t)s0 * NF + lane * 4]);
                float4 b4 = *reinterpret_cast<const float4*>(&Hs[(size_t)s1 * NF + lane * 4]);
                acc[0] += a4.x; acc[1] += a4.y; acc[2] += a4.z; acc[3] += a4.w;
                acc2[0] += b4.x; acc2[1] += b4.y; acc2[2] += b4.z; acc2[3] += b4.w;
            } else {
                float2 a2 = *reinterpret_cast<const float2*>(&Hs[(size_t)s0 * NF + lane * 2]);
                float2 b2 = *reinterpret_cast<const float2*>(&Hs[(size_t)s1 * NF + lane * 2]);
                acc[0] += a2.x; acc[1] += a2.y;
                acc2[0] += b2.x; acc2[1] += b2.y;
            }
        }
        if (i < end) {
            int s0 = g_csrc[i];
            if (VEC == 4) {
                float4 a4 = *reinterpret_cast<const float4*>(&Hs[(size_t)s0 * NF + lane * 4]);
                acc[0] += a4.x; acc[1] += a4.y; acc[2] += a4.z; acc[3] += a4.w;
            } else {
                float2 a2 = *reinterpret_cast<const float2*>(&Hs[(size_t)s0 * NF + lane * 2]);
                acc[0] += a2.x; acc[1] += a2.y;
            }
        }
        float dv = g_dinv[r];
        float z[VEC];
#pragma unroll
        for (int v = 0; v < VEC; v++) {
            z[v] = fmaf(acc[v] + acc2[v], dv, b[v]);
            s[v] += z[v];
            s2[v] += z[v] * z[v];
        }
        if (VEC == 4) {
            float4 o = make_float4(z[0], z[1], z[2], z[3]);
            *reinterpret_cast<float4*>(&g_z[(size_t)r * NF + lane * 4]) = o;
        } else {
            float2 o = make_float2(z[0], z[1]);
            *reinterpret_cast<float2*>(&g_z[(size_t)r * NF + lane * 2]) = o;
        }
    }
#pragma unroll
    for (int v = 0; v < VEC; v++) {
        scs[w][lane * VEC + v] = s[v];
        scss[w][lane * VEC + v] = s2[v];
    }
    __syncthreads();
    if (tid < NF) {
        float ts = 0.0f, ts2 = 0.0f;
#pragma unroll
        for (int ww = 0; ww < 8; ww++) { ts += scs[ww][tid]; ts2 += scss[ww][tid]; }
        atomicAdd(&CS[tid], ts);
        atomicAdd(&CSS[tid], ts2);
    }
}

// ---------------- BN + ReLU + mean-pool (layer 2 output) --------------------
__global__ void bn_pool_kernel(const float* __restrict__ gamma,
                               const float* __restrict__ beta,
                               const int* __restrict__ batch, int off) {
    int c = threadIdx.x;   // 64
    const float invN = 1.0f / (float)N_NODES;
    float m = g_cs2[c] * invN;
    float a = rsqrtf(g_css2[c] * invN - m * m + BN_EPS) * gamma[c];
    float bb = beta[c] - m * a;
    for (int r = blockIdx.x; r < N_NODES; r += gridDim.x) {
        float y = fmaxf(fmaf(g_z[(size_t)r * 64 + c], a, bb), 0.0f);
        atomicAdd(&g_pool[(size_t)batch[r] * 128 + off + c], y);
    }
}

// ---------------- MLP head ---------------------------------------------------
__global__ void mlp1_kernel(const float* __restrict__ Wf1, const float* __restrict__ bf1) {
    __shared__ float p[128];
    int g = blockIdx.x;
    int j = threadIdx.x;   // 64
    if (g == 0) { g_ms[j] = 0.0f; g_mss[j] = 0.0f; }
    float cv = g_gcnt[g]; if (cv < 1.0f) cv = 1.0f;
    float inv = 1.0f / cv;
    p[j]      = g_pool[(size_t)g * 128 + j] * inv;
    p[j + 64] = g_pool[(size_t)g * 128 + 64 + j] * inv;
    __syncthreads();
    float acc = bf1[j];
    for (int k = 0; k < 128; k++) acc += p[k] * Wf1[k * 64 + j];
    g_mlp[(size_t)g * 64 + j] = acc;
}

__global__ void mlp_stats_kernel() {
    int j = threadIdx.x;   // 64
    float s = 0.0f, s2 = 0.0f;
    for (int g = blockIdx.x; g < N_GRAPHS; g += gridDim.x) {
        float v = g_mlp[(size_t)g * 64 + j];
        s += v; s2 += v * v;
    }
    atomicAdd(&g_ms[j], s);
    atomicAdd(&g_mss[j], s2);
}

__global__ void mlp2_kernel(const float* __restrict__ gf1, const float* __restrict__ bef1,
                            const float* __restrict__ Wf2, const float* __restrict__ bf2,
                            float* __restrict__ out) {
    int g = blockIdx.x * blockDim.x + threadIdx.x;
    if (g >= N_GRAPHS) return;
    const float invG = 1.0f / (float)N_GRAPHS;
    float acc = 0.0f;
#pragma unroll 8
    for (int j = 0; j < 64; j++) {
        float m = g_ms[j] * invG;
        float v = g_mss[j] * invG - m * m;
        float y = (g_mlp[(size_t)g * 64 + j] - m) * rsqrtf(v + BN_EPS) * gf1[j] + bef1[j];
        y = fmaxf(y, 0.0f);
        acc += y * Wf2[j];
    }
    out[g] = acc + bf2[0];
}

// ---------------- launch -----------------------------------------------------

extern "C" void kernel_launch(void* const* d_in, const int* in_sizes, int n_in,
                              void* d_out, int out_size) {
    const float* xc    = (const float*)d_in[0];
    const float* xs    = (const float*)d_in[1];
    const int*   eic   = (const int*)d_in[2];
    const int*   eis   = (const int*)d_in[3];
    const int*   batch = (const int*)d_in[4];

    const float* Wb[2][2]  = {{(const float*)d_in[5],  (const float*)d_in[9]},
                              {(const float*)d_in[13], (const float*)d_in[17]}};
    const float* bb[2][2]  = {{(const float*)d_in[6],  (const float*)d_in[10]},
                              {(const float*)d_in[14], (const float*)d_in[18]}};
    const float* gb[2][2]  = {{(const float*)d_in[7],  (const float*)d_in[11]},
                              {(const float*)d_in[15], (const float*)d_in[19]}};
    const float* beb[2][2] = {{(const float*)d_in[8],  (const float*)d_in[12]},
                              {(const float*)d_in[16], (const float*)d_in[20]}};
    const float* Wf1  = (const float*)d_in[21];
    const float* bf1  = (const float*)d_in[22];
    const float* gf1  = (const float*)d_in[23];
    const float* bef1 = (const float*)d_in[24];
    const float* Wf2  = (const float*)d_in[25];
    const float* bf2  = (const float*)d_in[26];
    float* out = (float*)d_out;

    const int GEMM_BLOCKS = (N_NODES + 127) / 128;

    zero_pool_kernel<<<(N_GRAPHS * 128 + 255) / 256, 256>>>();
    count_batch_kernel<<<(N_NODES + 255) / 256, 256>>>(batch);

    for (int b = 0; b < 2; b++) {
        const float* X   = b ? xs : xc;
        const int*   src = b ? eis : eic;
        const int*   dst = src + N_EDGES;

        zero_cnt_kernel<<<(N_NODES + 255) / 256, 256>>>();
        count_dst_kernel<<<(N_EDGES + 255) / 256, 256>>>(dst);
        scan_kernel<<<1, 1024>>>();
        scatter_kernel<<<(N_EDGES + 255) / 256, 256>>>(src, dst);

        gemm1_kernel<<<GEMM_BLOCKS, 128>>>(X, Wb[b][0]);
        agg_kernel<128><<<2048, 256>>>(bb[b][0]);
        gemm2_kernel<<<GEMM_BLOCKS, 128>>>(Wb[b][1], gb[b][0], beb[b][0]);
        agg_kernel<64><<<2048, 256>>>(bb[b][1]);
        bn_pool_kernel<<<1024, 64>>>(gb[b][1], beb[b][1], batch, b * 64);
    }

    mlp1_kernel<<<N_GRAPHS, 64>>>(Wf1, bf1);
    mlp_stats_kernel<<<32, 64>>>();
    mlp2_kernel<<<(N_GRAPHS + 63) / 64, 64>>>(gf1, bef1, Wf2, bf2, out);
}

// round 7
// speedup vs baseline: 1.6143x; 1.3267x over previous
#include <cuda_runtime.h>

#define N_NODES 50000
#define N_EDGES 600000
#define F_IN 64
#define N_GRAPHS 2000
#define BN_EPS 1e-5f

#define SCAN_BT 512
#define SCAN_NB ((N_NODES + SCAN_BT - 1) / SCAN_BT)   // 98

// ---------------- scratch (device globals) ----------------------------------
// Feature buffers: single (branches processed sequentially) — ~64 MB total.
__device__ float g_h[(size_t)N_NODES * 128];   // hs = h * dinv (layer1)
__device__ float g_h2[(size_t)N_NODES * 64];   // hs2 (layer2)
__device__ float g_z[(size_t)N_NODES * 128];   // pre-BN buffer
// CSR metadata: double-buffered (built fused for both branches) — ~6.5 MB.
__device__ int   g_cnti[2][N_NODES];
__device__ float g_dinv[2][N_NODES];
__device__ int   g_off[2][N_NODES + 1];
__device__ int   g_head[2][N_NODES];
__device__ int   g_csrc[2][N_EDGES];
__device__ int   g_bsum[2][SCAN_NB];
__device__ float g_gcnt[N_GRAPHS];
__device__ float g_pool[N_GRAPHS * 128];
__device__ float g_cs[128], g_css[128];        // layer1 BN stats
__device__ float g_cs2[64], g_css2[64];        // layer2 BN stats
__device__ float g_mlp[N_GRAPHS * 64];
__device__ float g_ms[64], g_mss[64];

// ---------------- init + counting -------------------------------------------

__global__ void init_kernel(const int* __restrict__ batch) {
    int i = blockIdx.x * blockDim.x + threadIdx.x;
    if (i < N_GRAPHS * 128) g_pool[i] = 0.0f;
    if (i < N_GRAPHS) g_gcnt[i] = 0.0f;
    if (i < N_NODES) {
        g_cnti[0][i] = 0;
        g_cnti[1][i] = 0;
        atomicAdd(&g_gcnt[batch[i]], 1.0f);
    }
}

__global__ void count_dst_kernel(const int* __restrict__ eic, const int* __restrict__ eis) {
    int b = blockIdx.y;
    const int* dst = (b ? eis : eic) + N_EDGES;
    int i = blockIdx.x * blockDim.x + threadIdx.x;
    if (i < N_EDGES) atomicAdd(&g_cnti[b][dst[i]], 1);
}

// ---------------- 3-phase scan ----------------------------------------------

__global__ void scan_p1_kernel() {        // grid (SCAN_NB, 2), SCAN_BT thr
    __shared__ int ws[SCAN_BT / 32];
    int b = blockIdx.y;
    int i = blockIdx.x * SCAN_BT + threadIdx.x;
    int lane = threadIdx.x & 31, w = threadIdx.x >> 5;
    int v = (i < N_NODES) ? g_cnti[b][i] : 0;
#pragma unroll
    for (int o = 16; o > 0; o >>= 1) v += __shfl_down_sync(~0u, v, o);
    if (lane == 0) ws[w] = v;
    __syncthreads();
    if (threadIdx.x < SCAN_BT / 32) {
        int s = ws[threadIdx.x];
#pragma unroll
        for (int o = 8; o > 0; o >>= 1) s += __shfl_down_sync(0xFFFF, s, o);
        if (threadIdx.x == 0) g_bsum[b][blockIdx.x] = s;
    }
}

__global__ void scan_p2_kernel() {        // grid (2), 128 thr
    __shared__ int sm[128];
    int b = blockIdx.x;
    int i = threadIdx.x;
    int v = (i < SCAN_NB) ? g_bsum[b][i] : 0;
    int orig = v;
    sm[i] = v;
    __syncthreads();
    for (int o = 1; o < 128; o <<= 1) {
        int t = (i >= o) ? sm[i - o] : 0;
        __syncthreads();
        sm[i] += t;
        __syncthreads();
    }
    if (i < SCAN_NB) g_bsum[b][i] = sm[i] - orig;     // exclusive block offsets
    if (i == 0) g_off[b][N_NODES] = N_EDGES;
}

__global__ void scan_p3_kernel() {        // grid (SCAN_NB, 2), SCAN_BT thr
    __shared__ int ws[SCAN_BT / 32];
    int b = blockIdx.y;
    int i = blockIdx.x * SCAN_BT + threadIdx.x;
    int lane = threadIdx.x & 31, w = threadIdx.x >> 5;
    int c = (i < N_NODES) ? g_cnti[b][i] : 0;
    int v = c;
#pragma unroll
    for (int o = 1; o < 32; o <<= 1) {
        int t = __shfl_up_sync(~0u, v, o);
        if (lane >= o) v += t;
    }
    if (lane == 31) ws[w] = v;
    __syncthreads();
    if (w == 0 && lane < SCAN_BT / 32) {
        int s = ws[lane];
#pragma unroll
        for (int o = 1; o < SCAN_BT / 32; o <<= 1) {
            int t = __shfl_up_sync(0xFFFF, s, o);
            if (lane >= o) s += t;
        }
        ws[lane] = s;
    }
    __syncthreads();
    if (i < N_NODES) {
        int excl = g_bsum[b][blockIdx.x] + ((w > 0) ? ws[w - 1] : 0) + v - c;
        g_off[b][i] = excl;
        g_head[b][i] = excl;
        g_dinv[b][i] = rsqrtf((float)c + 1.0f);
    }
}

__global__ void scatter_kernel(const int* __restrict__ eic, const int* __restrict__ eis) {
    int b = blockIdx.y;
    const int* src = b ? eis : eic;
    const int* dst = src + N_EDGES;
    int e = blockIdx.x * blockDim.x + threadIdx.x;
    if (e < N_EDGES) {
        int slot = atomicAdd(&g_head[b][dst[e]], 1);
        g_csrc[b][slot] = src[e];
    }
}

// ---------------- GEMM1: hs = (X @ W1) * dinv; zeroes layer1 stats ----------
__global__ void gemm1_kernel(const float* __restrict__ X, const float* __restrict__ W,
                             int b) {
    __shared__ float Ws[64 * 128];
    int tid = threadIdx.x;
    for (int i = tid; i < 64 * 128; i += 128) Ws[i] = W[i];
    if (blockIdx.x == 0) { g_cs[tid] = 0.0f; g_css[tid] = 0.0f; }
    __syncthreads();
    int r = blockIdx.x * 128 + tid;
    if (r >= N_NODES) return;
    float dv = g_dinv[b][r];
    float xreg[64];
    {
        const float4* xr4 = reinterpret_cast<const float4*>(X + (size_t)r * 64);
#pragma unroll
        for (int k = 0; k < 16; k++) {
            float4 x4 = xr4[k];
            xreg[k * 4 + 0] = x4.x; xreg[k * 4 + 1] = x4.y;
            xreg[k * 4 + 2] = x4.z; xreg[k * 4 + 3] = x4.w;
        }
    }
    float* yr = g_h + (size_t)r * 128;
    for (int j0 = 0; j0 < 128; j0 += 32) {
        float acc[32];
#pragma unroll
        for (int jj = 0; jj < 32; jj++) acc[jj] = 0.0f;
#pragma unroll 4
        for (int k = 0; k < 64; k++) {
            float xk = xreg[k];
#pragma unroll
            for (int jj = 0; jj < 32; jj += 4) {
                float4 w4 = *reinterpret_cast<const float4*>(&Ws[k * 128 + j0 + jj]);
                acc[jj + 0] += xk * w4.x; acc[jj + 1] += xk * w4.y;
                acc[jj + 2] += xk * w4.z; acc[jj + 3] += xk * w4.w;
            }
        }
#pragma unroll
        for (int jj = 0; jj < 32; jj += 4) {
            float4 v = make_float4(acc[jj] * dv, acc[jj + 1] * dv,
                                   acc[jj + 2] * dv, acc[jj + 3] * dv);
            *reinterpret_cast<float4*>(&yr[j0 + jj]) = v;
        }
    }
}

// ---------------- GEMM2: hs2 = (relu(BN(z)) @ W2) * dinv; zeroes L2 stats ---
__global__ void gemm2_kernel(const float* __restrict__ W,
                             const float* __restrict__ gamma,
                             const float* __restrict__ beta, int b) {
    __shared__ float Ws[128 * 64];
    __shared__ float a_s[128], b_s[128];
    int tid = threadIdx.x;
    for (int i = tid; i < 128 * 64; i += 128) Ws[i] = W[i];
    {
        const float invN = 1.0f / (float)N_NODES;
        float m = g_cs[tid] * invN;
        float v = g_css[tid] * invN - m * m;
        float a = rsqrtf(v + BN_EPS) * gamma[tid];
        a_s[tid] = a;
        b_s[tid] = beta[tid] - m * a;
    }
    if (blockIdx.x == 0 && tid < 64) { g_cs2[tid] = 0.0f; g_css2[tid] = 0.0f; }
    __syncthreads();
    int r = blockIdx.x * 128 + tid;
    if (r >= N_NODES) return;
    float dv = g_dinv[b][r];
    const float* zr = g_z + (size_t)r * 128;
    float* yr = g_h2 + (size_t)r * 64;
    for (int j0 = 0; j0 < 64; j0 += 32) {
        float acc[32];
#pragma unroll
        for (int jj = 0; jj < 32; jj++) acc[jj] = 0.0f;
#pragma unroll 4
        for (int k = 0; k < 128; k++) {
            float xk = fmaxf(fmaf(zr[k], a_s[k], b_s[k]), 0.0f);
#pragma unroll
            for (int jj = 0; jj < 32; jj += 4) {
                float4 w4 = *reinterpret_cast<const float4*>(&Ws[k * 64 + j0 + jj]);
                acc[jj + 0] += xk * w4.x; acc[jj + 1] += xk * w4.y;
                acc[jj + 2] += xk * w4.z; acc[jj + 3] += xk * w4.w;
            }
        }
#pragma unroll
        for (int jj = 0; jj < 32; jj += 4) {
            float4 v = make_float4(acc[jj] * dv, acc[jj + 1] * dv,
                                   acc[jj + 2] * dv, acc[jj + 3] * dv);
            *reinterpret_cast<float4*>(&yr[j0 + jj]) = v;
        }
    }
}

// ---------------- gather aggregation + BN stats ------------------------------
template <int NF>
__global__ void agg_kernel(const float* __restrict__ bias, int b) {
    const int VEC = NF / 32;
    const float* Hs = (NF == 128) ? g_h : g_h2;
    float* CS  = (NF == 128) ? g_cs  : g_cs2;
    float* CSS = (NF == 128) ? g_css : g_css2;
    const int* off = g_off[b];
    const int* csrc = g_csrc[b];
    __shared__ float scs[8][NF];
    __shared__ float scss[8][NF];
    int tid = threadIdx.x, lane = tid & 31, w = tid >> 5;
    float bb[VEC], s[VEC], s2[VEC];
#pragma unroll
    for (int v = 0; v < VEC; v++) {
        bb[v] = bias[lane * VEC + v];
        s[v] = 0.0f; s2[v] = 0.0f;
    }
    for (int r = blockIdx.x * 8 + w; r < N_NODES; r += gridDim.x * 8) {
        int beg = off[r], end = off[r + 1];
        float acc[VEC], acc2[VEC];
        if (VEC == 4) {
            float4 h4 = *reinterpret_cast<const float4*>(&Hs[(size_t)r * NF + lane * 4]);
            acc[0] = h4.x; acc[1] = h4.y; acc[2] = h4.z; acc[3] = h4.w;
        } else {
            float2 h2 = *reinterpret_cast<const float2*>(&Hs[(size_t)r * NF + lane * 2]);
            acc[0] = h2.x; acc[1] = h2.y;
        }
#pragma unroll
        for (int v = 0; v < VEC; v++) acc2[v] = 0.0f;
        int i = beg;
        for (; i + 1 < end; i += 2) {
            int s0 = csrc[i], s1 = csrc[i + 1];
            if (VEC == 4) {
                float4 a4 = *reinterpret_cast<const float4*>(&Hs[(size_t)s0 * NF + lane * 4]);
                float4 b4 = *reinterpret_cast<const float4*>(&Hs[(size_t)s1 * NF + lane * 4]);
                acc[0] += a4.x; acc[1] += a4.y; acc[2] += a4.z; acc[3] += a4.w;
                acc2[0] += b4.x; acc2[1] += b4.y; acc2[2] += b4.z; acc2[3] += b4.w;
            } else {
                float2 a2 = *reinterpret_cast<const float2*>(&Hs[(size_t)s0 * NF + lane * 2]);
                float2 b2 = *reinterpret_cast<const float2*>(&Hs[(size_t)s1 * NF + lane * 2]);
                acc[0] += a2.x; acc[1] += a2.y;
                acc2[0] += b2.x; acc2[1] += b2.y;
            }
        }
        if (i < end) {
            int s0 = csrc[i];
            if (VEC == 4) {
                float4 a4 = *reinterpret_cast<const float4*>(&Hs[(size_t)s0 * NF + lane * 4]);
                acc[0] += a4.x; acc[1] += a4.y; acc[2] += a4.z; acc[3] += a4.w;
            } else {
                float2 a2 = *reinterpret_cast<const float2*>(&Hs[(size_t)s0 * NF + lane * 2]);
                acc[0] += a2.x; acc[1] += a2.y;
            }
        }
        float dv = g_dinv[b][r];
        float z[VEC];
#pragma unroll
        for (int v = 0; v < VEC; v++) {
            z[v] = fmaf(acc[v] + acc2[v], dv, bb[v]);
            s[v] += z[v];
            s2[v] += z[v] * z[v];
        }
        if (VEC == 4) {
            float4 o = make_float4(z[0], z[1], z[2], z[3]);
            *reinterpret_cast<float4*>(&g_z[(size_t)r * NF + lane * 4]) = o;
        } else {
            float2 o = make_float2(z[0], z[1]);
            *reinterpret_cast<float2*>(&g_z[(size_t)r * NF + lane * 2]) = o;
        }
    }
#pragma unroll
    for (int v = 0; v < VEC; v++) {
        scs[w][lane * VEC + v] = s[v];
        scss[w][lane * VEC + v] = s2[v];
    }
    __syncthreads();
    if (tid < NF) {
        float ts = 0.0f, ts2 = 0.0f;
#pragma unroll
        for (int ww = 0; ww < 8; ww++) { ts += scs[ww][tid]; ts2 += scss[ww][tid]; }
        atomicAdd(&CS[tid], ts);
        atomicAdd(&CSS[tid], ts2);
    }
}

// ---------------- BN + ReLU + mean-pool (layer 2 output) --------------------
__global__ void bn_pool_kernel(const float* __restrict__ gamma,
                               const float* __restrict__ beta,
                               const int* __restrict__ batch, int off) {
    int c = threadIdx.x;   // 64
    const float invN = 1.0f / (float)N_NODES;
    float m = g_cs2[c] * invN;
    float a = rsqrtf(g_css2[c] * invN - m * m + BN_EPS) * gamma[c];
    float bb = beta[c] - m * a;
    for (int r = blockIdx.x; r < N_NODES; r += gridDim.x) {
        float y = fmaxf(fmaf(g_z[(size_t)r * 64 + c], a, bb), 0.0f);
        atomicAdd(&g_pool[(size_t)batch[r] * 128 + off + c], y);
    }
}

// ---------------- MLP head ---------------------------------------------------
__global__ void mlp1_kernel(const float* __restrict__ Wf1, const float* __restrict__ bf1) {
    __shared__ float p[128];
    int g = blockIdx.x;
    int j = threadIdx.x;   // 64
    if (g == 0) { g_ms[j] = 0.0f; g_mss[j] = 0.0f; }
    float cv = g_gcnt[g]; if (cv < 1.0f) cv = 1.0f;
    float inv = 1.0f / cv;
    p[j]      = g_pool[(size_t)g * 128 + j] * inv;
    p[j + 64] = g_pool[(size_t)g * 128 + 64 + j] * inv;
    __syncthreads();
    float acc = bf1[j];
    for (int k = 0; k < 128; k++) acc += p[k] * Wf1[k * 64 + j];
    g_mlp[(size_t)g * 64 + j] = acc;
}

__global__ void mlp_stats_kernel() {
    int j = threadIdx.x;   // 64
    float s = 0.0f, s2 = 0.0f;
    for (int g = blockIdx.x; g < N_GRAPHS; g += gridDim.x) {
        float v = g_mlp[(size_t)g * 64 + j];
        s += v; s2 += v * v;
    }
    atomicAdd(&g_ms[j], s);
    atomicAdd(&g_mss[j], s2);
}

__global__ void mlp2_kernel(const float* __restrict__ gf1, const float* __restrict__ bef1,
                            const float* __restrict__ Wf2, const float* __restrict__ bf2,
                            float* __restrict__ out) {
    int g = blockIdx.x * blockDim.x + threadIdx.x;
    if (g >= N_GRAPHS) return;
    const float invG = 1.0f / (float)N_GRAPHS;
    float acc = 0.0f;
#pragma unroll 8
    for (int j = 0; j < 64; j++) {
        float m = g_ms[j] * invG;
        float v = g_mss[j] * invG - m * m;
        float y = (g_mlp[(size_t)g * 64 + j] - m) * rsqrtf(v + BN_EPS) * gf1[j] + bef1[j];
        y = fmaxf(y, 0.0f);
        acc += y * Wf2[j];
    }
    out[g] = acc + bf2[0];
}

// ---------------- launch -----------------------------------------------------

extern "C" void kernel_launch(void* const* d_in, const int* in_sizes, int n_in,
                              void* d_out, int out_size) {
    const float* xc    = (const float*)d_in[0];
    const float* xs    = (const float*)d_in[1];
    const int*   eic   = (const int*)d_in[2];
    const int*   eis   = (const int*)d_in[3];
    const int*   batch = (const int*)d_in[4];

    const float* Wb[2][2]  = {{(const float*)d_in[5],  (const float*)d_in[9]},
                              {(const float*)d_in[13], (const float*)d_in[17]}};
    const float* bb[2][2]  = {{(const float*)d_in[6],  (const float*)d_in[10]},
                              {(const float*)d_in[14], (const float*)d_in[18]}};
    const float* gb[2][2]  = {{(const float*)d_in[7],  (const float*)d_in[11]},
                              {(const float*)d_in[15], (const float*)d_in[19]}};
    const float* beb[2][2] = {{(const float*)d_in[8],  (const float*)d_in[12]},
                              {(const float*)d_in[16], (const float*)d_in[20]}};
    const float* Wf1  = (const float*)d_in[21];
    const float* bf1  = (const float*)d_in[22];
    const float* gf1  = (const float*)d_in[23];
    const float* bef1 = (const float*)d_in[24];
    const float* Wf2  = (const float*)d_in[25];
    const float* bf2  = (const float*)d_in[26];
    float* out = (float*)d_out;

    const int GEMM_BLOCKS = (N_NODES + 127) / 128;

    // ---- fused CSR build for both branches ----
    init_kernel<<<(N_GRAPHS * 128 + 255) / 256, 256>>>(batch);
    count_dst_kernel<<<dim3((N_EDGES + 255) / 256, 2), 256>>>(eic, eis);
    scan_p1_kernel<<<dim3(SCAN_NB, 2), SCAN_BT>>>();
    scan_p2_kernel<<<2, 128>>>();
    scan_p3_kernel<<<dim3(SCAN_NB, 2), SCAN_BT>>>();
    scatter_kernel<<<dim3((N_EDGES + 255) / 256, 2), 256>>>(eic, eis);

    // ---- per-branch compute (sequential, single feature buffers) ----
    for (int b = 0; b < 2; b++) {
        const float* X = b ? xs : xc;
        gemm1_kernel<<<GEMM_BLOCKS, 128>>>(X, Wb[b][0], b);
        agg_kernel<128><<<2048, 256>>>(bb[b][0], b);
        gemm2_kernel<<<GEMM_BLOCKS, 128>>>(Wb[b][1], gb[b][0], beb[b][0], b);
        agg_kernel<64><<<2048, 256>>>(bb[b][1], b);
        bn_pool_kernel<<<1024, 64>>>(gb[b][1], beb[b][1], batch, b * 64);
    }

    mlp1_kernel<<<N_GRAPHS, 64>>>(Wf1, bf1);
    mlp_stats_kernel<<<32, 64>>>();
    mlp2_kernel<<<(N_GRAPHS + 63) / 64, 64>>>(gf1, bef1, Wf2, bf2, out);
}

// round 10
// speedup vs baseline: 2.5014x; 1.5495x over previous
#include <cuda_runtime.h>

#define N_NODES 50000
#define N_EDGES 600000
#define F_IN 64
#define N_GRAPHS 2000
#define BN_EPS 1e-5f

#define SCAN_BT 512
#define SCAN_NB ((N_NODES + SCAN_BT - 1) / SCAN_BT)   // 98

// ---------------- scratch (device globals) ----------------------------------
__device__ float g_h[(size_t)N_NODES * 128];   // hs = h * dinv (layer1)
__device__ float g_h2[(size_t)N_NODES * 64];   // hs2 (layer2)
__device__ float g_z[(size_t)N_NODES * 128];   // pre-BN buffer
__device__ int   g_cnti[2][N_NODES];
__device__ float g_dinv[2][N_NODES];
__device__ int   g_off[2][N_NODES + 1];
__device__ int   g_head[2][N_NODES];
__device__ int   g_csrc[2][N_EDGES];
__device__ int   g_bsum[2][SCAN_NB];
__device__ float g_gcnt[N_GRAPHS];
__device__ float g_pool[N_GRAPHS * 128];
__device__ float g_cs[128], g_css[128];        // layer1 BN stats
__device__ float g_cs2[64], g_css2[64];        // layer2 BN stats
__device__ float g_mlp[N_GRAPHS * 64];
__device__ float g_ms[64], g_mss[64];

// ---------------- init + counting -------------------------------------------

__global__ void init_kernel(const int* __restrict__ batch) {
    int i = blockIdx.x * blockDim.x + threadIdx.x;
    if (i < N_GRAPHS * 128) g_pool[i] = 0.0f;
    if (i < N_GRAPHS) g_gcnt[i] = 0.0f;
    if (i < N_NODES) {
        g_cnti[0][i] = 0;
        g_cnti[1][i] = 0;
        atomicAdd(&g_gcnt[batch[i]], 1.0f);
    }
}

__global__ void count_dst_kernel(const int* __restrict__ eic, const int* __restrict__ eis) {
    int b = blockIdx.y;
    const int* dst = (b ? eis : eic) + N_EDGES;
    int i = blockIdx.x * blockDim.x + threadIdx.x;
    if (i < N_EDGES) atomicAdd(&g_cnti[b][dst[i]], 1);
}

// ---------------- 3-phase scan ----------------------------------------------

__global__ void scan_p1_kernel() {
    __shared__ int ws[SCAN_BT / 32];
    int b = blockIdx.y;
    int i = blockIdx.x * SCAN_BT + threadIdx.x;
    int lane = threadIdx.x & 31, w = threadIdx.x >> 5;
    int v = (i < N_NODES) ? g_cnti[b][i] : 0;
#pragma unroll
    for (int o = 16; o > 0; o >>= 1) v += __shfl_down_sync(~0u, v, o);
    if (lane == 0) ws[w] = v;
    __syncthreads();
    if (threadIdx.x < SCAN_BT / 32) {
        int s = ws[threadIdx.x];
#pragma unroll
        for (int o = 8; o > 0; o >>= 1) s += __shfl_down_sync(0xFFFF, s, o);
        if (threadIdx.x == 0) g_bsum[b][blockIdx.x] = s;
    }
}

__global__ void scan_p2_kernel() {
    __shared__ int sm[128];
    int b = blockIdx.x;
    int i = threadIdx.x;
    int v = (i < SCAN_NB) ? g_bsum[b][i] : 0;
    int orig = v;
    sm[i] = v;
    __syncthreads();
    for (int o = 1; o < 128; o <<= 1) {
        int t = (i >= o) ? sm[i - o] : 0;
        __syncthreads();
        sm[i] += t;
        __syncthreads();
    }
    if (i < SCAN_NB) g_bsum[b][i] = sm[i] - orig;
    if (i == 0) g_off[b][N_NODES] = N_EDGES;
}

__global__ void scan_p3_kernel() {
    __shared__ int ws[SCAN_BT / 32];
    int b = blockIdx.y;
    int i = blockIdx.x * SCAN_BT + threadIdx.x;
    int lane = threadIdx.x & 31, w = threadIdx.x >> 5;
    int c = (i < N_NODES) ? g_cnti[b][i] : 0;
    int v = c;
#pragma unroll
    for (int o = 1; o < 32; o <<= 1) {
        int t = __shfl_up_sync(~0u, v, o);
        if (lane >= o) v += t;
    }
    if (lane == 31) ws[w] = v;
    __syncthreads();
    if (w == 0 && lane < SCAN_BT / 32) {
        int s = ws[lane];
#pragma unroll
        for (int o = 1; o < SCAN_BT / 32; o <<= 1) {
            int t = __shfl_up_sync(0xFFFF, s, o);
            if (lane >= o) s += t;
        }
        ws[lane] = s;
    }
    __syncthreads();
    if (i < N_NODES) {
        int excl = g_bsum[b][blockIdx.x] + ((w > 0) ? ws[w - 1] : 0) + v - c;
        g_off[b][i] = excl;
        g_head[b][i] = excl;
        g_dinv[b][i] = rsqrtf((float)c + 1.0f);
    }
}

__global__ void scatter_kernel(const int* __restrict__ eic, const int* __restrict__ eis) {
    int b = blockIdx.y;
    const int* src = b ? eis : eic;
    const int* dst = src + N_EDGES;
    int e = blockIdx.x * blockDim.x + threadIdx.x;
    if (e < N_EDGES) {
        int slot = atomicAdd(&g_head[b][dst[e]], 1);
        g_csrc[b][slot] = src[e];
    }
}

// ---------------- tiled GEMM -------------------------------------------------
// Block: 256 thr, tile M=128 x N=NOUT, K chunked by 32. Thread tile 8 x (NOUT/16).
// LAYER==1: reads X, writes g_h   (out = (X @ W) * dinv);       zeroes layer1 stats.
// LAYER==2: reads g_z through fused BN+ReLU, writes g_h2;       zeroes layer2 stats.
template <int K, int NOUT, int LAYER>
__global__ void gemm_tiled(const float* __restrict__ X, const float* __restrict__ W,
                           const float* __restrict__ gamma, const float* __restrict__ beta,
                           int b) {
    constexpr int TC = NOUT / 16;          // 8 (L1) or 4 (L2)
    __shared__ float Xs[128][36];          // 32-k chunk, padded
    __shared__ float Wsh[32][NOUT];
    __shared__ float a_s[128], b_s[128];
    int tid = threadIdx.x;
    int tx = tid & 15, ty = tid >> 4;      // 16 x 16
    int row0 = blockIdx.x * 128;

    if (LAYER == 2) {
        const float invN = 1.0f / (float)N_NODES;
        for (int c = tid; c < K; c += 256) {
            float m = g_cs[c] * invN;
            float v = g_css[c] * invN - m * m;
            float a = rsqrtf(v + BN_EPS) * gamma[c];
            a_s[c] = a;
            b_s[c] = beta[c] - m * a;
        }
        if (blockIdx.x == 0 && tid < 64) { g_cs2[tid] = 0.0f; g_css2[tid] = 0.0f; }
    } else {
        if (blockIdx.x == 0 && tid < 128) { g_cs[tid] = 0.0f; g_css[tid] = 0.0f; }
    }

    const float* Xp = (LAYER == 1) ? X : g_z;
    float* Out = (LAYER == 1) ? g_h : g_h2;

    float acc[8][TC];
#pragma unroll
    for (int i = 0; i < 8; i++)
#pragma unroll
        for (int j = 0; j < TC; j++) acc[i][j] = 0.0f;

    for (int k0 = 0; k0 < K; k0 += 32) {
        __syncthreads();   // previous compute done (and LAYER2 a_s ready on 1st pass)
        // stage X chunk: 128 rows x 32 k
#pragma unroll
        for (int it = 0; it < 4; it++) {
            int idx = tid + 256 * it;          // 1024 float4
            int r = idx >> 3, c4 = (idx & 7) * 4;
            float4 x4 = make_float4(0.f, 0.f, 0.f, 0.f);
            int gr = row0 + r;
            if (gr < N_NODES)
                x4 = *reinterpret_cast<const float4*>(&Xp[(size_t)gr * K + k0 + c4]);
            if (LAYER == 2) {
                x4.x = fmaxf(fmaf(x4.x, a_s[k0 + c4 + 0], b_s[k0 + c4 + 0]), 0.0f);
                x4.y = fmaxf(fmaf(x4.y, a_s[k0 + c4 + 1], b_s[k0 + c4 + 1]), 0.0f);
                x4.z = fmaxf(fmaf(x4.z, a_s[k0 + c4 + 2], b_s[k0 + c4 + 2]), 0.0f);
                x4.w = fmaxf(fmaf(x4.w, a_s[k0 + c4 + 3], b_s[k0 + c4 + 3]), 0.0f);
            }
            *reinterpret_cast<float4*>(&Xs[r][c4]) = x4;
        }
        // stage W chunk: 32 x NOUT
#pragma unroll
        for (int it = 0; it < NOUT / 32; it++) {
            int idx = tid + 256 * it;          // 32*NOUT/4 float4
            int r = idx / (NOUT / 4), c4 = (idx % (NOUT / 4)) * 4;
            *reinterpret_cast<float4*>(&Wsh[r][c4]) =
                *reinterpret_cast<const float4*>(&W[(size_t)(k0 + r) * NOUT + c4]);
        }
        __syncthreads();
#pragma unroll 4
        for (int k = 0; k < 32; k++) {
            float av[8];
#pragma unroll
            for (int i = 0; i < 8; i++) av[i] = Xs[ty * 8 + i][k];
            float bv[TC];
#pragma unroll
            for (int j = 0; j < TC; j += 4) {
                float4 w4 = *reinterpret_cast<const float4*>(&Wsh[k][tx * TC + j]);
                bv[j] = w4.x; bv[j + 1] = w4.y; bv[j + 2] = w4.z; bv[j + 3] = w4.w;
            }
#pragma unroll
            for (int i = 0; i < 8; i++)
#pragma unroll
                for (int j = 0; j < TC; j++)
                    acc[i][j] = fmaf(av[i], bv[j], acc[i][j]);
        }
    }
#pragma unroll
    for (int i = 0; i < 8; i++) {
        int r = row0 + ty * 8 + i;
        if (r >= N_NODES) continue;
        float dv = g_dinv[b][r];
        float* yr = Out + (size_t)r * NOUT + tx * TC;
#pragma unroll
        for (int j = 0; j < TC; j += 4) {
            float4 v = make_float4(acc[i][j] * dv, acc[i][j + 1] * dv,
                                   acc[i][j + 2] * dv, acc[i][j + 3] * dv);
            *reinterpret_cast<float4*>(&yr[j]) = v;
        }
    }
}

// ---------------- gather aggregation + BN stats ------------------------------
template <int NF>
__global__ void agg_kernel(const float* __restrict__ bias, int b) {
    const int VEC = NF / 32;
    const float* Hs = (NF == 128) ? g_h : g_h2;
    float* CS  = (NF == 128) ? g_cs  : g_cs2;
    float* CSS = (NF == 128) ? g_css : g_css2;
    const int* off = g_off[b];
    const int* csrc = g_csrc[b];
    __shared__ float scs[8][NF];
    __shared__ float scss[8][NF];
    int tid = threadIdx.x, lane = tid & 31, w = tid >> 5;
    float bb[VEC], s[VEC], s2[VEC];
#pragma unroll
    for (int v = 0; v < VEC; v++) {
        bb[v] = bias[lane * VEC + v];
        s[v] = 0.0f; s2[v] = 0.0f;
    }
    for (int r = blockIdx.x * 8 + w; r < N_NODES; r += gridDim.x * 8) {
        int beg = off[r], end = off[r + 1];
        float acc[VEC];
        if (VEC == 4) {
            float4 h4 = *reinterpret_cast<const float4*>(&Hs[(size_t)r * NF + lane * 4]);
            acc[0] = h4.x; acc[1] = h4.y; acc[2] = h4.z; acc[3] = h4.w;
        } else {
            float2 h2 = *reinterpret_cast<const float2*>(&Hs[(size_t)r * NF + lane * 2]);
            acc[0] = h2.x; acc[1] = h2.y;
        }
        // warp-batched neighbor gather: coalesced index load + shfl broadcast
        for (int base = beg; base < end; base += 32) {
            int m = end - base; if (m > 32) m = 32;
            int idx = (lane < m) ? csrc[base + lane] : 0;
            for (int j = 0; j < m; j++) {
                int s0 = __shfl_sync(~0u, idx, j);
                if (VEC == 4) {
                    float4 a4 = *reinterpret_cast<const float4*>(&Hs[(size_t)s0 * NF + lane * 4]);
                    acc[0] += a4.x; acc[1] += a4.y; acc[2] += a4.z; acc[3] += a4.w;
                } else {
                    float2 a2 = *reinterpret_cast<const float2*>(&Hs[(size_t)s0 * NF + lane * 2]);
                    acc[0] += a2.x; acc[1] += a2.y;
                }
            }
        }
        float dv = g_dinv[b][r];
        float z[VEC];
#pragma unroll
        for (int v = 0; v < VEC; v++) {
            z[v] = fmaf(acc[v], dv, bb[v]);
            s[v] += z[v];
            s2[v] += z[v] * z[v];
        }
        if (VEC == 4) {
            float4 o = make_float4(z[0], z[1], z[2], z[3]);
            *reinterpret_cast<float4*>(&g_z[(size_t)r * NF + lane * 4]) = o;
        } else {
            float2 o = make_float2(z[0], z[1]);
            *reinterpret_cast<float2*>(&g_z[(size_t)r * NF + lane * 2]) = o;
        }
    }
#pragma unroll
    for (int v = 0; v < VEC; v++) {
        scs[w][lane * VEC + v] = s[v];
        scss[w][lane * VEC + v] = s2[v];
    }
    __syncthreads();
    if (tid < NF) {
        float ts = 0.0f, ts2 = 0.0f;
#pragma unroll
        for (int ww = 0; ww < 8; ww++) { ts += scs[ww][tid]; ts2 += scss[ww][tid]; }
        atomicAdd(&CS[tid], ts);
        atomicAdd(&CSS[tid], ts2);
    }
}

// ---------------- BN + ReLU + segmented mean-pool (sorted batch) ------------
__global__ void bn_pool_kernel(const float* __restrict__ gamma,
                               const float* __restrict__ beta,
                               const int* __restrict__ batch, int off) {
    int c = threadIdx.x;   // 64
    const float invN = 1.0f / (float)N_NODES;
    float m = g_cs2[c] * invN;
    float a = rsqrtf(g_css2[c] * invN - m * m + BN_EPS) * gamma[c];
    float bb = beta[c] - m * a;
    const int RPB = (N_NODES + gridDim.x - 1) / gridDim.x;
    int r0 = blockIdx.x * RPB;
    int r1 = r0 + RPB; if (r1 > N_NODES) r1 = N_NODES;
    if (r0 >= r1) return;
    int cur = batch[r0];
    float acc = 0.0f;
    for (int r = r0; r < r1; r++) {
        int g = batch[r];
        if (g != cur) {
            atomicAdd(&g_pool[(size_t)cur * 128 + off + c], acc);
            acc = 0.0f; cur = g;
        }
        acc += fmaxf(fmaf(g_z[(size_t)r * 64 + c], a, bb), 0.0f);
    }
    atomicAdd(&g_pool[(size_t)cur * 128 + off + c], acc);
}

// ---------------- MLP head ---------------------------------------------------
__global__ void mlp1_kernel(const float* __restrict__ Wf1, const float* __restrict__ bf1) {
    __shared__ float p[128];
    int g = blockIdx.x;
    int j = threadIdx.x;   // 64
    if (g == 0) { g_ms[j] = 0.0f; g_mss[j] = 0.0f; }
    float cv = g_gcnt[g]; if (cv < 1.0f) cv = 1.0f;
    float inv = 1.0f / cv;
    p[j]      = g_pool[(size_t)g * 128 + j] * inv;
    p[j + 64] = g_pool[(size_t)g * 128 + 64 + j] * inv;
    __syncthreads();
    float acc = bf1[j];
    for (int k = 0; k < 128; k++) acc += p[k] * Wf1[k * 64 + j];
    g_mlp[(size_t)g * 64 + j] = acc;
}

__global__ void mlp_stats_kernel() {
    int j = threadIdx.x;   // 64
    float s = 0.0f, s2 = 0.0f;
    for (int g = blockIdx.x; g < N_GRAPHS; g += gridDim.x) {
        float v = g_mlp[(size_t)g * 64 + j];
        s += v; s2 += v * v;
    }
    atomicAdd(&g_ms[j], s);
    atomicAdd(&g_mss[j], s2);
}

__global__ void mlp2_kernel(const float* __restrict__ gf1, const float* __restrict__ bef1,
                            const float* __restrict__ Wf2, const float* __restrict__ bf2,
                            float* __restrict__ out) {
    int g = blockIdx.x * blockDim.x + threadIdx.x;
    if (g >= N_GRAPHS) return;
    const float invG = 1.0f / (float)N_GRAPHS;
    float acc = 0.0f;
#pragma unroll 8
    for (int j = 0; j < 64; j++) {
        float m = g_ms[j] * invG;
        float v = g_mss[j] * invG - m * m;
        float y = (g_mlp[(size_t)g * 64 + j] - m) * rsqrtf(v + BN_EPS) * gf1[j] + bef1[j];
        y = fmaxf(y, 0.0f);
        acc += y * Wf2[j];
    }
    out[g] = acc + bf2[0];
}

// ---------------- launch -----------------------------------------------------

extern "C" void kernel_launch(void* const* d_in, const int* in_sizes, int n_in,
                              void* d_out, int out_size) {
    const float* xc    = (const float*)d_in[0];
    const float* xs    = (const float*)d_in[1];
    const int*   eic   = (const int*)d_in[2];
    const int*   eis   = (const int*)d_in[3];
    const int*   batch = (const int*)d_in[4];

    const float* Wb[2][2]  = {{(const float*)d_in[5],  (const float*)d_in[9]},
                              {(const float*)d_in[13], (const float*)d_in[17]}};
    const float* bb[2][2]  = {{(const float*)d_in[6],  (const float*)d_in[10]},
                              {(const float*)d_in[14], (const float*)d_in[18]}};
    const float* gb[2][2]  = {{(const float*)d_in[7],  (const float*)d_in[11]},
                              {(const float*)d_in[15], (const float*)d_in[19]}};
    const float* beb[2][2] = {{(const float*)d_in[8],  (const float*)d_in[12]},
                              {(const float*)d_in[16], (const float*)d_in[20]}};
    const float* Wf1  = (const float*)d_in[21];
    const float* bf1  = (const float*)d_in[22];
    const float* gf1  = (const float*)d_in[23];
    const float* bef1 = (const float*)d_in[24];
    const float* Wf2  = (const float*)d_in[25];
    const float* bf2  = (const float*)d_in[26];
    float* out = (float*)d_out;

    const int GEMM_BLOCKS = (N_NODES + 127) / 128;   // 391

    // ---- fused CSR build for both branches ----
    init_kernel<<<(N_GRAPHS * 128 + 255) / 256, 256>>>(batch);
    count_dst_kernel<<<dim3((N_EDGES + 255) / 256, 2), 256>>>(eic, eis);
    scan_p1_kernel<<<dim3(SCAN_NB, 2), SCAN_BT>>>();
    scan_p2_kernel<<<2, 128>>>();
    scan_p3_kernel<<<dim3(SCAN_NB, 2), SCAN_BT>>>();
    scatter_kernel<<<dim3((N_EDGES + 255) / 256, 2), 256>>>(eic, eis);

    // ---- per-branch compute (sequential, single feature buffers) ----
    for (int b = 0; b < 2; b++) {
        const float* X = b ? xs : xc;
        gemm_tiled<64, 128, 1><<<GEMM_BLOCKS, 256>>>(X, Wb[b][0], nullptr, nullptr, b);
        agg_kernel<128><<<2048, 256>>>(bb[b][0], b);
        gemm_tiled<128, 64, 2><<<GEMM_BLOCKS, 256>>>(nullptr, Wb[b][1], gb[b][0], beb[b][0], b);
        agg_kernel<64><<<2048, 256>>>(bb[b][1], b);
        bn_pool_kernel<<<1024, 64>>>(gb[b][1], beb[b][1], batch, b * 64);
    }

    mlp1_kernel<<<N_GRAPHS, 64>>>(Wf1, bf1);
    mlp_stats_kernel<<<32, 64>>>();
    mlp2_kernel<<<(N_GRAPHS + 63) / 64, 64>>>(gf1, bef1, Wf2, bf2, out);
}